// round 1
// baseline (speedup 1.0000x reference)
#include <cuda_runtime.h>
#include <cuda_bf16.h>

// Problem constants
#define BATCH   128
#define T_STEPS 256
#define IN_F    1024
#define OUT_C   512
#define M_TOTAL (BATCH * T_STEPS)   // 32768

// SNN hyperparameters
#define V_TH      0.4f
#define V_RESET   0.0f
#define LEAK      0.01f
#define REFR_LEAK 0.01f
#define REFR_POT  0.0f
#define STD_POT   0.0f
#define REFRAC    2.0f

// 64 MB scratch for I = x @ W, laid out [B*T, C] row-major (row = b*T + t)
__device__ float g_I[(size_t)M_TOTAL * OUT_C];

// ---------------------------------------------------------------------------
// SGEMM: C[M,N] = A[M,K] @ B[K,N], fp32.
// M=32768, N=512, K=1024. BM=128, BN=128, BK=8, 256 threads, 8x8 microtile.
// ---------------------------------------------------------------------------
#define BM 128
#define BN 128
#define BK 8
#define TM 8
#define TN 8

__global__ __launch_bounds__(256, 2)
void snn_gemm_kernel(const float* __restrict__ A,
                     const float* __restrict__ B) {
    __shared__ float As[BK][BM];   // A tile, transposed: As[k][m]
    __shared__ float Bs[BK][BN];   // B tile: Bs[k][n]

    const int tid = threadIdx.x;
    const int blockRow = blockIdx.y;   // 0..255
    const int blockCol = blockIdx.x;   // 0..3

    // microtile coordinates: 16 x 16 thread grid
    const int tCol = tid % (BN / TN);  // 0..15
    const int tRow = tid / (BN / TN);  // 0..15

    // A global-load mapping: each thread loads one float4 per BK-slab
    const int aRow = tid >> 1;          // 0..127
    const int aCol = (tid & 1) * 4;     // 0 or 4
    // B global-load mapping
    const int bRow = tid >> 5;          // 0..7
    const int bCol = (tid & 31) * 4;    // 0..124

    const float* Ablk = A + (size_t)blockRow * BM * IN_F;
    const float* Bblk = B + blockCol * BN;
    float* Cblk = g_I + (size_t)blockRow * BM * OUT_C + blockCol * BN;

    float acc[TM][TN];
    #pragma unroll
    for (int i = 0; i < TM; i++)
        #pragma unroll
        for (int j = 0; j < TN; j++)
            acc[i][j] = 0.0f;

    float ra[TM], rb[TN];

    for (int k0 = 0; k0 < IN_F; k0 += BK) {
        // load A slab (128 x 8) transposed into smem
        float4 a4 = *(const float4*)(Ablk + (size_t)aRow * IN_F + k0 + aCol);
        As[aCol + 0][aRow] = a4.x;
        As[aCol + 1][aRow] = a4.y;
        As[aCol + 2][aRow] = a4.z;
        As[aCol + 3][aRow] = a4.w;
        // load B slab (8 x 128)
        float4 b4 = *(const float4*)(Bblk + (size_t)(k0 + bRow) * OUT_C + bCol);
        *(float4*)&Bs[bRow][bCol] = b4;
        __syncthreads();

        #pragma unroll
        for (int k = 0; k < BK; k++) {
            #pragma unroll
            for (int i = 0; i < TM; i++) ra[i] = As[k][tRow * TM + i];
            #pragma unroll
            for (int j = 0; j < TN; j++) rb[j] = Bs[k][tCol * TN + j];
            #pragma unroll
            for (int i = 0; i < TM; i++)
                #pragma unroll
                for (int j = 0; j < TN; j++)
                    acc[i][j] = fmaf(ra[i], rb[j], acc[i][j]);
        }
        __syncthreads();
    }

    #pragma unroll
    for (int i = 0; i < TM; i++) {
        #pragma unroll
        for (int j = 0; j < TN; j += 4) {
            float4 v = make_float4(acc[i][j], acc[i][j + 1],
                                   acc[i][j + 2], acc[i][j + 3]);
            *(float4*)(Cblk + (size_t)(tRow * TM + i) * OUT_C + tCol * TN + j) = v;
        }
    }
}

// ---------------------------------------------------------------------------
// Per-neuron sequential scan over T. One thread per (b, c) neuron.
// Loads of I are independent of the recurrent state -> unroll for MLP.
// Faithful replication of reference step semantics:
//   masks m_std/m_abs/m_rel are computed from the OLD mode, so the three
//   branches are mutually exclusive per step (if/else chain is exact).
// ---------------------------------------------------------------------------
__global__ __launch_bounds__(256)
void snn_scan_kernel(float* __restrict__ out) {
    const int idx = blockIdx.x * blockDim.x + threadIdx.x;  // 0..65535
    const int b = idx >> 9;        // / OUT_C
    const int c = idx & (OUT_C - 1);

    const float* Ip = g_I + ((size_t)b * T_STEPS) * OUT_C + c;

    float V = 0.0f, refr = 0.0f, sc = 0.0f;
    int mode = 0;

    #pragma unroll 8
    for (int t = 0; t < T_STEPS; t++) {
        const float I = Ip[(size_t)t * OUT_C];
        if (mode == 0) {
            // standard: integrate, leak, floor at STD_POT, spike
            V = V + I - LEAK;
            if (V < STD_POT) V = STD_POT;
            if (V - V_TH > 0.0f) {
                sc += 1.0f;
                V = V_RESET;
                refr = REFRAC;
                mode = 1;
            }
        } else if (mode == 1) {
            // absolute refractory: count down
            refr = fmaxf(refr - 1.0f, 0.0f);
            if (refr <= 0.0f) mode = 2;
            if (V < REFR_POT) V = REFR_POT;
        } else {
            // relative refractory: recover toward standard
            V += REFR_LEAK;
            if (V < REFR_POT) V = REFR_POT;
            if (V > STD_POT) mode = 0;
        }
    }

    out[idx] = sc;
}

// ---------------------------------------------------------------------------
extern "C" void kernel_launch(void* const* d_in, const int* in_sizes, int n_in,
                              void* d_out, int out_size) {
    const float* x_seq = (const float*)d_in[0];  // [B, T, F] == [M_TOTAL, IN_F]
    const float* W     = (const float*)d_in[1];  // [IN_F, OUT_C]
    float* out = (float*)d_out;                  // [B, C] spike counts

    dim3 gemmGrid(OUT_C / BN, M_TOTAL / BM);     // (4, 256)
    snn_gemm_kernel<<<gemmGrid, 256>>>(x_seq, W);

    snn_scan_kernel<<<(BATCH * OUT_C) / 256, 256>>>(out);
}